// round 9
// baseline (speedup 1.0000x reference)
#include <cuda_runtime.h>
#include <cstdint>

#define BB   16
#define NPP  4096
#define CIN  64
#define MM   1024
#define KK   64
#define HID  64
#define OUTD 128
#define NC   (BB*MM)
#define R2   0.04f

#define OFF_C 2097152         /* NC*OUTD */
#define OFF_B 2146304         /* OFF_C + NC*3 */

#define NF1    256            /* f1 tasks: 256 rows each              */
#define NTNBR  1024           /* nbr tasks: 16 centers each (256 thr) */
#define NTMLP  4096           /* mlp tasks: 4 centers each (256 thr)  */
#define GRID   152
#define NTHR   512

/* smem layout (floats) */
#define SBUF0 0
#define SBUF1 16384
#define SW2   32768           /* W2:   4096            */
#define SW3D  36864           /* W3 duplicated: 16384  */
#define SWP   53248           /* 192                   */
#define SB2   53440           /* 64                    */
#define SB3   53504           /* 128                   */
#define SMTOT 53632           /* 214,528 B             */

#define NBAR(ex) asm volatile("bar.sync %0, %1;" :: "r"((ex)+1), "r"(256) : "memory")

typedef unsigned long long ull;

__device__ int   g_fps[NC];
__device__ int   g_nbr[NC*KK];
__device__ int   g_cnt[NC];
__device__ float g_F1[(size_t)BB*NPP*HID];
__device__ int   g_cf1, g_cnbr, g_cmlp, g_f1done;
__device__ int   g_prog[BB];
__device__ int   g_flag[NTNBR];

__device__ __forceinline__ float d2f(float ax,float ay,float az,float bx,float by,float bz){
    float dx=__fsub_rn(ax,bx), dy=__fsub_rn(ay,by), dz=__fsub_rn(az,bz);
    return __fadd_rn(__fadd_rn(__fmul_rn(dx,dx),__fmul_rn(dy,dy)),__fmul_rn(dz,dz));
}

/* ---- packed fp32x2 helpers (sm_103a, per-lane IEEE-exact) ---- */
__device__ __forceinline__ void fma2(ull &d, ull a, ull b){
    asm("fma.rn.f32x2 %0, %1, %2, %0;" : "+l"(d) : "l"(a), "l"(b));
}
__device__ __forceinline__ ull add2(ull a, ull b){
    ull r; asm("add.rn.f32x2 %0, %1, %2;" : "=l"(r) : "l"(a), "l"(b)); return r;
}
__device__ __forceinline__ ull mul2(ull a, ull b){
    ull r; asm("mul.rn.f32x2 %0, %1, %2;" : "=l"(r) : "l"(a), "l"(b)); return r;
}
__device__ __forceinline__ ull splat2(float x){
    ull r; unsigned u = __float_as_uint(x);
    asm("mov.b64 %0, {%1, %1};" : "=l"(r) : "r"(u)); return r;
}
__device__ __forceinline__ void unpack2(ull v, float &lo, float &hi){
    unsigned a,b; asm("mov.b64 {%0, %1}, %2;" : "=r"(a), "=r"(b) : "l"(v));
    lo = __uint_as_float(a); hi = __uint_as_float(b);
}
__device__ __forceinline__ ull pack2(float lo, float hi){
    ull r;
    asm("mov.b64 %0, {%1, %2};" : "=l"(r) : "r"(__float_as_uint(lo)), "r"(__float_as_uint(hi)));
    return r;
}
__device__ __forceinline__ int vload(const int* p){ return *(volatile const int*)p; }

// ---------------------------------------------------------------------------
// FPS producer (unchanged from R8)
// ---------------------------------------------------------------------------
__device__ void do_fps(float* sm, int tid, int b, const float* __restrict__ point){
    float* px = sm; float* py = sm + NPP; float* pz = sm + 2*NPP;
    __shared__ ull wpS[2][32];
    int lane = tid & 31, warp = tid >> 5;

    const float* P = point + (size_t)b*NPP*3;
    float x[8], y[8], z[8], d[8];
    #pragma unroll
    for (int r = 0; r < 8; r++){
        int i = tid + r*NTHR;
        float a0 = P[i*3+0], a1 = P[i*3+1], a2 = P[i*3+2];
        px[i] = a0; py[i] = a1; pz[i] = a2;
        x[r] = a0; y[r] = a1; z[r] = a2;
        d[r] = 3.402823466e38f;
    }
    ull xp[4], yp[4], zp[4];
    #pragma unroll
    for (int g = 0; g < 4; g++){
        xp[g] = pack2(x[2*g], x[2*g+1]);
        yp[g] = pack2(y[2*g], y[2*g+1]);
        zp[g] = pack2(z[2*g], z[2*g+1]);
    }
    if (tid < 64) ((ull*)wpS)[tid] = 0ull;
    if (tid == 0) g_fps[b*MM] = 0;
    __syncthreads();

    int last = 0, par = 0;
    for (int m = 1; m < MM; m++){
        float cx = px[last], cy = py[last], cz = pz[last];
        ull ncx = splat2(-cx), ncy = splat2(-cy), ncz = splat2(-cz);

        float bv = -1.f;
        #pragma unroll
        for (int g = 0; g < 4; g++){
            ull dx = add2(xp[g], ncx);
            ull dy = add2(yp[g], ncy);
            ull dz = add2(zp[g], ncz);
            ull ss = add2(add2(mul2(dx,dx), mul2(dy,dy)), mul2(dz,dz));
            float s0, s1; unpack2(ss, s0, s1);
            float v0 = fminf(d[2*g  ], s0); d[2*g  ] = v0;
            float v1 = fminf(d[2*g+1], s1); d[2*g+1] = v1;
            bv = fmaxf(bv, fmaxf(v0, v1));
        }
        unsigned bits = __float_as_uint(bv);
        unsigned wmax = __reduce_max_sync(0xffffffffu, bits);
        unsigned cand = 0xffffffffu;
        if (bits == wmax){
            #pragma unroll
            for (int r = 7; r >= 0; r--)
                if (d[r] == bv) cand = (unsigned)(tid + r*NTHR);
        }
        unsigned widx = __reduce_min_sync(0xffffffffu, cand);
        if (lane == 0) wpS[par][warp] = (((ull)wmax) << 32) | widx;
        __syncthreads();
        ull v = wpS[par][lane];
        unsigned hb = (unsigned)(v >> 32), lw = (unsigned)v;
        unsigned gmax = __reduce_max_sync(0xffffffffu, hb);
        unsigned c2   = (hb == gmax) ? lw : 0xffffffffu;
        unsigned gidx = __reduce_min_sync(0xffffffffu, c2);
        last = (int)gidx;
        if (tid == 0){
            g_fps[b*MM + m] = last;
            if ((m & 15) == 15){ __threadfence(); atomicExch(&g_prog[b], m + 1); }
        }
        par ^= 1;
    }
}

// ---------------------------------------------------------------------------
// F1 task (unchanged from R8)
// ---------------------------------------------------------------------------
__device__ void do_f1(float* ws, int ltid, int ex, int id,
                      const float* __restrict__ xyz,
                      const float* __restrict__ W1,
                      const float* __restrict__ b1){
    float* W1s = ws;
    for (int i = ltid; i < CIN*HID; i += 256) W1s[i] = W1[i];
    if (ltid < HID) W1s[4096 + ltid] = b1[ltid];
    NBAR(ex);

    int row = id*256 + ltid;
    float acc[HID];
    #pragma unroll
    for (int o = 0; o < HID; o++) acc[o] = W1s[4096 + o];
    const float4* xr = (const float4*)(xyz + (size_t)row*CIN);
    #pragma unroll
    for (int q = 0; q < 16; q++){
        float4 xv = xr[q];
        float av[4] = {xv.x, xv.y, xv.z, xv.w};
        #pragma unroll
        for (int t = 0; t < 4; t++){
            float a = av[t];
            const float4* w = (const float4*)(W1s + (q*4+t)*HID);
            #pragma unroll
            for (int u = 0; u < 16; u++){
                float4 wv4 = w[u];
                acc[4*u]   = fmaf(a, wv4.x, acc[4*u]);
                acc[4*u+1] = fmaf(a, wv4.y, acc[4*u+1]);
                acc[4*u+2] = fmaf(a, wv4.z, acc[4*u+2]);
                acc[4*u+3] = fmaf(a, wv4.w, acc[4*u+3]);
            }
        }
    }
    float4* o4 = (float4*)(g_F1 + (size_t)row*HID);
    #pragma unroll
    for (int u = 0; u < 16; u++)
        o4[u] = make_float4(acc[4*u], acc[4*u+1], acc[4*u+2], acc[4*u+3]);

    __threadfence();
    NBAR(ex);
    if (ltid == 0) atomicAdd(&g_f1done, 1);
}

// ---------------------------------------------------------------------------
// nbr task (unchanged from R8, precise gate)
// ---------------------------------------------------------------------------
__device__ void do_nbr(float* ws, int ltid, int ex, int id,
                       const float* __restrict__ point, float* __restrict__ out){
    float* px = ws; float* py = ws + NPP; float* pz = ws + 2*NPP;
    ull* keys = (ull*)(ws + 3*NPP);
    __shared__ int ncand[2][16];

    int cloud = id & 15, chunk = id >> 4;
    int c0g = cloud*MM + chunk*16;

    if (ltid == 0){
        while (vload(&g_prog[cloud]) < chunk*16 + 16) __nanosleep(128);
    }
    NBAR(ex);

    const float* P = point + (size_t)cloud*NPP*3;
    for (int i = ltid; i < NPP; i += 256){
        px[i] = P[i*3+0]; py[i] = P[i*3+1]; pz[i] = P[i*3+2];
    }
    if (ltid < 16) ncand[ex][ltid] = 0;
    NBAR(ex);

    for (int ci = 0; ci < 16; ci++){
        int c  = c0g + ci;
        int cl = __ldcg(&g_fps[c]);
        float cx = px[cl], cy = py[cl], cz = pz[cl];
        for (int i = ltid; i < NPP; i += 256){
            float d2 = d2f(px[i], py[i], pz[i], cx, cy, cz);
            if (d2 < R2){
                int p = atomicAdd(&ncand[ex][ci], 1);
                if (p < 512)
                    keys[p] = (((ull)__float_as_uint(d2)) << 32) | (unsigned)i;
            }
        }
        NBAR(ex);
        int n   = min(ncand[ex][ci], 512);
        int cnt = min(n, KK);
        if (ltid == 0) g_cnt[c] = cnt;
        for (int i = ltid; i < n; i += 256){
            ull k = keys[i];
            int rank = 0;
            for (int jj = 0; jj < n; jj++) rank += (keys[jj] < k);
            if (rank < KK) g_nbr[c*KK + rank] = (int)(k & 0xffffffffu);
        }
        for (int i = cnt + ltid; i < KK; i += 256) g_nbr[c*KK + i] = cl;
        NBAR(ex);
    }
    if (ltid < 16){
        int c = c0g + ltid; int cl = __ldcg(&g_fps[c]);
        out[OFF_C + c*3 + 0] = px[cl];
        out[OFF_C + c*3 + 1] = py[cl];
        out[OFF_C + c*3 + 2] = pz[cl];
        out[OFF_B + c] = (float)cloud;
    }
    __threadfence();
    NBAR(ex);
    if (ltid == 0) atomicExch(&g_flag[id], 1);
}

// ---------------------------------------------------------------------------
// mlp task (256 thr): 4 centers. New tiling: thread covers points
// p = 4*lane + 128*g + j (g in {0,1}, j in 0..3) -> A via 2x LDS.128/k.
// h3 weights from duplicated smem W3D -> packed pairs, no splats.
// ---------------------------------------------------------------------------
__device__ void do_mlp(float* ws, float* smw, int ltid, int ex, int id,
                       const float* __restrict__ point, float* __restrict__ out){
    float* buf  = ws;                 /* 16384 : [64][256] h1 then h2 */
    float* W2s  = smw + SW2;
    float* W3Ds = smw + SW3D;
    float* Wp   = smw + SWP;
    float* b2s  = smw + SB2;
    float* b3s  = smw + SB3;

    if (ltid == 0){
        int fl = ((id >> 6) << 4) | (id & 15);
        while (!(vload(&g_flag[fl]) && vload(&g_f1done) >= NF1)) __nanosleep(128);
    }
    NBAR(ex);

    int lane = ltid & 31;
    int cloud = id & 15;
    int seg   = id >> 4;
    int c0s   = cloud*MM + seg*4;
    const float* P = point + (size_t)cloud*NPP*3;

    int ci = ltid >> 6;
    int cl = __ldcg(&g_fps[c0s + ci]);
    int j  = __ldcg(&g_nbr[c0s*KK + ltid]);

    float dx = __fsub_rn(P[j*3+0], P[cl*3+0]);
    float dy = __fsub_rn(P[j*3+1], P[cl*3+1]);
    float dz = __fsub_rn(P[j*3+2], P[cl*3+2]);

    float h1[HID];
    const float4* fv = (const float4*)(g_F1 + (size_t)(cloud*NPP + j)*HID);
    #pragma unroll
    for (int q = 0; q < 16; q++){
        float4 v = __ldcg(fv + q);
        h1[4*q]=v.x; h1[4*q+1]=v.y; h1[4*q+2]=v.z; h1[4*q+3]=v.w;
    }
    #pragma unroll
    for (int i = 0; i < HID; i++){
        float v = h1[i];
        v = fmaf(dx, Wp[i],       v);
        v = fmaf(dy, Wp[64 + i],  v);
        v = fmaf(dz, Wp[128 + i], v);
        h1[i] = fmaxf(v, 0.f);
    }
    #pragma unroll
    for (int k = 0; k < HID; k++) buf[k*256 + ltid] = h1[k];
    NBAR(ex);

    int ow = (ltid >> 5)*8;
    const float* aptr = buf + 4*lane;

    /* h2 = relu(h1 @ W2 + b2) : A new pairs, B splat (W2 undup) */
    {
        ull acc[2][2][8];
        #pragma unroll
        for (int o = 0; o < 8; o++){
            ull bv = splat2(b2s[ow + o]);
            acc[0][0][o] = bv; acc[0][1][o] = bv;
            acc[1][0][o] = bv; acc[1][1][o] = bv;
        }
        #pragma unroll 4
        for (int k = 0; k < HID; k++){
            ulonglong2 A0 = *(const ulonglong2*)(aptr + k*256);
            ulonglong2 A1 = *(const ulonglong2*)(aptr + k*256 + 128);
            float4 w0 = *(const float4*)(W2s + k*64 + ow);
            float4 w1 = *(const float4*)(W2s + k*64 + ow + 4);
            ull B2[8] = { splat2(w0.x), splat2(w0.y), splat2(w0.z), splat2(w0.w),
                          splat2(w1.x), splat2(w1.y), splat2(w1.z), splat2(w1.w) };
            #pragma unroll
            for (int o = 0; o < 8; o++){
                fma2(acc[0][0][o], A0.x, B2[o]);
                fma2(acc[0][1][o], A0.y, B2[o]);
                fma2(acc[1][0][o], A1.x, B2[o]);
                fma2(acc[1][1][o], A1.y, B2[o]);
            }
        }
        NBAR(ex);
        /* relu + store h2 transposed rows (ow+o), pairs at 4*lane(+128) */
        #pragma unroll
        for (int o = 0; o < 8; o++){
            float l0,h0,l1,h1v,l2,h2v,l3,h3v;
            unpack2(acc[0][0][o], l0, h0);  unpack2(acc[0][1][o], l1, h1v);
            unpack2(acc[1][0][o], l2, h2v); unpack2(acc[1][1][o], l3, h3v);
            ulonglong2 s0, s1;
            s0.x = pack2(fmaxf(l0,0.f), fmaxf(h0,0.f));
            s0.y = pack2(fmaxf(l1,0.f), fmaxf(h1v,0.f));
            s1.x = pack2(fmaxf(l2,0.f), fmaxf(h2v,0.f));
            s1.y = pack2(fmaxf(l3,0.f), fmaxf(h3v,0.f));
            *(ulonglong2*)(buf + (ow+o)*256 + 4*lane)       = s0;
            *(ulonglong2*)(buf + (ow+o)*256 + 4*lane + 128) = s1;
        }
        NBAR(ex);
    }

    int lgrp = lane & 15;      /* slot base / 4          */
    int cg   = lane >> 4;      /* center sub-index 0/1   */
    int cntA = __ldcg(&g_cnt[c0s + cg]);       /* g=0 center */
    int cntB = __ldcg(&g_cnt[c0s + cg + 2]);   /* g=1 center */

    /* h3 = relu(h2 @ W3 + b3), W3 from duplicated smem (packed pairs) */
    #pragma unroll
    for (int pass = 0; pass < 2; pass++){
        ull acc[2][2][8];
        #pragma unroll
        for (int o = 0; o < 8; o++){
            ull bv = splat2(b3s[pass*64 + ow + o]);
            acc[0][0][o] = bv; acc[0][1][o] = bv;
            acc[1][0][o] = bv; acc[1][1][o] = bv;
        }
        #pragma unroll 4
        for (int k = 0; k < HID; k++){
            ulonglong2 A0 = *(const ulonglong2*)(aptr + k*256);
            ulonglong2 A1 = *(const ulonglong2*)(aptr + k*256 + 128);
            const float* wd = W3Ds + k*256 + 2*(pass*64 + ow);
            ulonglong2 wq0 = *(const ulonglong2*)(wd);
            ulonglong2 wq1 = *(const ulonglong2*)(wd + 4);
            ulonglong2 wq2 = *(const ulonglong2*)(wd + 8);
            ulonglong2 wq3 = *(const ulonglong2*)(wd + 12);
            ull B2[8] = { wq0.x, wq0.y, wq1.x, wq1.y, wq2.x, wq2.y, wq3.x, wq3.y };
            #pragma unroll
            for (int o = 0; o < 8; o++){
                fma2(acc[0][0][o], A0.x, B2[o]);
                fma2(acc[0][1][o], A0.y, B2[o]);
                fma2(acc[1][0][o], A1.x, B2[o]);
                fma2(acc[1][1][o], A1.y, B2[o]);
            }
        }
        /* masked relu + max over this thread's 4 points per center,
           then 16-lane butterfly (bits 1,2,4,8 stay within lane-group) */
        #pragma unroll
        for (int g = 0; g < 2; g++){
            int cnt = g ? cntB : cntA;
            int s0 = 4*lgrp, s1 = s0+1, s2 = s0+2, s3 = s0+3;
            #pragma unroll
            for (int o = 0; o < 8; o++){
                float lo, hi, lo2, hi2;
                unpack2(acc[g][0][o], lo, hi);
                unpack2(acc[g][1][o], lo2, hi2);
                lo  = (s0 < cnt) ? fmaxf(lo, 0.f)  : -3.402823466e38f;
                hi  = (s1 < cnt) ? fmaxf(hi, 0.f)  : -3.402823466e38f;
                lo2 = (s2 < cnt) ? fmaxf(lo2, 0.f) : -3.402823466e38f;
                hi2 = (s3 < cnt) ? fmaxf(hi2, 0.f) : -3.402823466e38f;
                float m = fmaxf(fmaxf(lo, hi), fmaxf(lo2, hi2));
                m = fmaxf(m, __shfl_xor_sync(0xffffffffu, m, 1));
                m = fmaxf(m, __shfl_xor_sync(0xffffffffu, m, 2));
                m = fmaxf(m, __shfl_xor_sync(0xffffffffu, m, 4));
                m = fmaxf(m, __shfl_xor_sync(0xffffffffu, m, 8));
                if (lgrp == 0)
                    out[(size_t)(c0s + cg + 2*g)*OUTD + pass*64 + ow + o] = m;
            }
        }
    }
}

// ---------------------------------------------------------------------------
// Init: reset queues/flags.
// ---------------------------------------------------------------------------
__global__ void init_kernel(){
    int t = blockIdx.x*blockDim.x + threadIdx.x;
    if (t == 0){ g_cf1 = 0; g_cnbr = 0; g_cmlp = 0; g_f1done = 0; }
    if (t < BB) g_prog[t] = 0;
    if (t < NTNBR) g_flag[t] = 0;
}

// ---------------------------------------------------------------------------
// Mega kernel.
// ---------------------------------------------------------------------------
__global__ void __launch_bounds__(NTHR,1) mega_kernel(
        const float* __restrict__ point, const float* __restrict__ xyz,
        const float* __restrict__ W1, const float* __restrict__ b1,
        const float* __restrict__ W2, const float* __restrict__ b2,
        const float* __restrict__ W3, const float* __restrict__ b3,
        float* __restrict__ out){
    extern __shared__ float sm[];
    int tid = threadIdx.x;
    __shared__ int s_ph[2], s_id[2];

    if (blockIdx.x < BB) do_fps(sm + SBUF0, tid, blockIdx.x, point);

    /* persistent weights: W2 plain, W3 duplicated for packed-pair loads */
    for (int i = tid; i < 4096; i += NTHR) sm[SW2 + i] = W2[i];
    for (int i = tid; i < 8192; i += NTHR){
        float w = W3[i];
        int k = i >> 7, o = i & 127;
        sm[SW3D + (k << 8) + 2*o    ] = w;
        sm[SW3D + (k << 8) + 2*o + 1] = w;
    }
    if (tid < 192) sm[SWP + tid] = W1[4096 + tid];
    if (tid < 64)  sm[SB2 + tid] = b2[tid];
    if (tid < 128) sm[SB3 + tid] = b3[tid];
    __syncthreads();

    int ex   = tid >> 8;
    int ltid = tid & 255;
    float* ws = sm + (ex ? SBUF1 : SBUF0);

    for (;;){
        if (ltid == 0){
            int ph = -1, id = -1;
            if (vload(&g_cf1) < NF1){
                int t = atomicAdd(&g_cf1, 1);
                if (t < NF1){ ph = 0; id = t; }
            }
            if (ph < 0){
                int t = vload(&g_cnbr);
                if (t < NTNBR){
                    int cloud = t & 15, chunk = t >> 4;
                    if (vload(&g_prog[cloud]) >= chunk*16 + 16){
                        t = atomicAdd(&g_cnbr, 1);
                        if (t < NTNBR){ ph = 1; id = t; }
                    }
                }
            }
            if (ph < 0){
                int t = vload(&g_cmlp);
                if (t < NTMLP && vload(&g_f1done) >= NF1){
                    int fl = ((t >> 6) << 4) | (t & 15);
                    if (vload(&g_flag[fl])){
                        t = atomicAdd(&g_cmlp, 1);
                        if (t < NTMLP){ ph = 2; id = t; }
                    }
                }
            }
            if (ph < 0){
                if (vload(&g_cf1) >= NF1 && vload(&g_cnbr) >= NTNBR && vload(&g_cmlp) >= NTMLP)
                    ph = 3;
                else { __nanosleep(256); ph = 4; }
            }
            s_ph[ex] = ph; s_id[ex] = id;
        }
        NBAR(ex);
        int ph = s_ph[ex], id = s_id[ex];
        if (ph == 3) break;
        if      (ph == 0) do_f1 (ws, ltid, ex, id, xyz, W1, b1);
        else if (ph == 1) do_nbr(ws, ltid, ex, id, point, out);
        else if (ph == 2) do_mlp(ws, sm, ltid, ex, id, point, out);
        NBAR(ex);
    }
}

extern "C" void kernel_launch(void* const* d_in, const int* in_sizes, int n_in,
                              void* d_out, int out_size){
    const float *xyz=nullptr, *point=nullptr, *W1=nullptr, *b1=nullptr,
                *W2=nullptr, *b2=nullptr, *W3=nullptr, *b3=nullptr;
    int n64 = 0;
    for (int i = 0; i < n_in; i++){
        switch (in_sizes[i]){
            case 4194304: xyz   = (const float*)d_in[i]; break;
            case 196608:  point = (const float*)d_in[i]; break;
            case 4288:    W1    = (const float*)d_in[i]; break;
            case 4096:    W2    = (const float*)d_in[i]; break;
            case 8192:    W3    = (const float*)d_in[i]; break;
            case 64:      if (n64++ == 0) b1 = (const float*)d_in[i];
                          else            b2 = (const float*)d_in[i]; break;
            case 128:     b3    = (const float*)d_in[i]; break;
            default: break;
        }
    }
    float* out = (float*)d_out;

    int smem = SMTOT*(int)sizeof(float);   /* 214,528 B */
    cudaFuncSetAttribute(mega_kernel, cudaFuncAttributeMaxDynamicSharedMemorySize, smem);

    init_kernel<<<4, 256>>>();
    mega_kernel<<<GRID, NTHR, smem>>>(point, xyz, W1, b1, W2, b2, W3, b3, out);
}

// round 11
// speedup vs baseline: 1.6683x; 1.6683x over previous
#include <cuda_runtime.h>
#include <cstdint>

#define BB   16
#define NPP  4096
#define CIN  64
#define MM   1024
#define KK   64
#define HID  64
#define OUTD 128
#define NC   (BB*MM)
#define R2   0.04f

#define OFF_C 2097152         /* NC*OUTD */
#define OFF_B 2146304         /* OFF_C + NC*3 */

#define NF1    256            /* f1 tasks: 256 rows each              */
#define NTNBR  1024           /* nbr tasks: 16 centers each (256 thr) */
#define NTMLP  4096           /* mlp tasks: 4 centers each (256 thr)  */
#define GRID   152
#define NTHR   512

/* smem layout (floats) */
#define SBUF0 0
#define SBUF1 16384
#define SW2D  32768           /* W2 duplicated: 8192  */
#define SWP   40960           /* 192                  */
#define SB2   41152           /* 64                   */
#define SB3   41216           /* 128                  */
#define SMTOT 41344           /* 165,376 B            */

#define NBAR(ex) asm volatile("bar.sync %0, %1;" :: "r"((ex)+1), "r"(256) : "memory")

typedef unsigned long long ull;

__device__ int   g_fps[NC];
__device__ int   g_nbr[NC*KK];
__device__ int   g_cnt[NC];
__device__ float g_F1[(size_t)BB*NPP*HID];
__device__ int   g_cf1, g_cnbr, g_cmlp, g_f1done;
__device__ int   g_prog[BB];
__device__ int   g_flag[NTNBR];

__device__ __forceinline__ float d2f(float ax,float ay,float az,float bx,float by,float bz){
    float dx=__fsub_rn(ax,bx), dy=__fsub_rn(ay,by), dz=__fsub_rn(az,bz);
    return __fadd_rn(__fadd_rn(__fmul_rn(dx,dx),__fmul_rn(dy,dy)),__fmul_rn(dz,dz));
}

/* ---- packed fp32x2 helpers (sm_103a, per-lane IEEE-exact) ---- */
__device__ __forceinline__ void fma2(ull &d, ull a, ull b){
    asm("fma.rn.f32x2 %0, %1, %2, %0;" : "+l"(d) : "l"(a), "l"(b));
}
__device__ __forceinline__ ull add2(ull a, ull b){
    ull r; asm("add.rn.f32x2 %0, %1, %2;" : "=l"(r) : "l"(a), "l"(b)); return r;
}
__device__ __forceinline__ ull mul2(ull a, ull b){
    ull r; asm("mul.rn.f32x2 %0, %1, %2;" : "=l"(r) : "l"(a), "l"(b)); return r;
}
__device__ __forceinline__ ull splat2(float x){
    ull r; unsigned u = __float_as_uint(x);
    asm("mov.b64 %0, {%1, %1};" : "=l"(r) : "r"(u)); return r;
}
__device__ __forceinline__ void unpack2(ull v, float &lo, float &hi){
    unsigned a,b; asm("mov.b64 {%0, %1}, %2;" : "=r"(a), "=r"(b) : "l"(v));
    lo = __uint_as_float(a); hi = __uint_as_float(b);
}
__device__ __forceinline__ ull pack2(float lo, float hi){
    ull r;
    asm("mov.b64 %0, {%1, %2};" : "=l"(r) : "r"(__float_as_uint(lo)), "r"(__float_as_uint(hi)));
    return r;
}
__device__ __forceinline__ int vload(const int* p){ return *(volatile const int*)p; }

// ---------------------------------------------------------------------------
// FPS producer (unchanged from R8)
// ---------------------------------------------------------------------------
__device__ void do_fps(float* sm, int tid, int b, const float* __restrict__ point){
    float* px = sm; float* py = sm + NPP; float* pz = sm + 2*NPP;
    __shared__ ull wpS[2][32];
    int lane = tid & 31, warp = tid >> 5;

    const float* P = point + (size_t)b*NPP*3;
    float x[8], y[8], z[8], d[8];
    #pragma unroll
    for (int r = 0; r < 8; r++){
        int i = tid + r*NTHR;
        float a0 = P[i*3+0], a1 = P[i*3+1], a2 = P[i*3+2];
        px[i] = a0; py[i] = a1; pz[i] = a2;
        x[r] = a0; y[r] = a1; z[r] = a2;
        d[r] = 3.402823466e38f;
    }
    ull xp[4], yp[4], zp[4];
    #pragma unroll
    for (int g = 0; g < 4; g++){
        xp[g] = pack2(x[2*g], x[2*g+1]);
        yp[g] = pack2(y[2*g], y[2*g+1]);
        zp[g] = pack2(z[2*g], z[2*g+1]);
    }
    if (tid < 64) ((ull*)wpS)[tid] = 0ull;
    if (tid == 0) g_fps[b*MM] = 0;
    __syncthreads();

    int last = 0, par = 0;
    for (int m = 1; m < MM; m++){
        float cx = px[last], cy = py[last], cz = pz[last];
        ull ncx = splat2(-cx), ncy = splat2(-cy), ncz = splat2(-cz);

        float bv = -1.f;
        #pragma unroll
        for (int g = 0; g < 4; g++){
            ull dx = add2(xp[g], ncx);
            ull dy = add2(yp[g], ncy);
            ull dz = add2(zp[g], ncz);
            ull ss = add2(add2(mul2(dx,dx), mul2(dy,dy)), mul2(dz,dz));
            float s0, s1; unpack2(ss, s0, s1);
            float v0 = fminf(d[2*g  ], s0); d[2*g  ] = v0;
            float v1 = fminf(d[2*g+1], s1); d[2*g+1] = v1;
            bv = fmaxf(bv, fmaxf(v0, v1));
        }
        unsigned bits = __float_as_uint(bv);
        unsigned wmax = __reduce_max_sync(0xffffffffu, bits);
        unsigned cand = 0xffffffffu;
        if (bits == wmax){
            #pragma unroll
            for (int r = 7; r >= 0; r--)
                if (d[r] == bv) cand = (unsigned)(tid + r*NTHR);
        }
        unsigned widx = __reduce_min_sync(0xffffffffu, cand);
        if (lane == 0) wpS[par][warp] = (((ull)wmax) << 32) | widx;
        __syncthreads();
        ull v = wpS[par][lane];
        unsigned hb = (unsigned)(v >> 32), lw = (unsigned)v;
        unsigned gmax = __reduce_max_sync(0xffffffffu, hb);
        unsigned c2   = (hb == gmax) ? lw : 0xffffffffu;
        unsigned gidx = __reduce_min_sync(0xffffffffu, c2);
        last = (int)gidx;
        if (tid == 0){
            g_fps[b*MM + m] = last;
            if ((m & 15) == 15){ __threadfence(); atomicExch(&g_prog[b], m + 1); }
        }
        par ^= 1;
    }
}

// ---------------------------------------------------------------------------
// F1 task (unchanged from R8)
// ---------------------------------------------------------------------------
__device__ void do_f1(float* ws, int ltid, int ex, int id,
                      const float* __restrict__ xyz,
                      const float* __restrict__ W1,
                      const float* __restrict__ b1){
    float* W1s = ws;
    for (int i = ltid; i < CIN*HID; i += 256) W1s[i] = W1[i];
    if (ltid < HID) W1s[4096 + ltid] = b1[ltid];
    NBAR(ex);

    int row = id*256 + ltid;
    float acc[HID];
    #pragma unroll
    for (int o = 0; o < HID; o++) acc[o] = W1s[4096 + o];
    const float4* xr = (const float4*)(xyz + (size_t)row*CIN);
    #pragma unroll
    for (int q = 0; q < 16; q++){
        float4 xv = xr[q];
        float av[4] = {xv.x, xv.y, xv.z, xv.w};
        #pragma unroll
        for (int t = 0; t < 4; t++){
            float a = av[t];
            const float4* w = (const float4*)(W1s + (q*4+t)*HID);
            #pragma unroll
            for (int u = 0; u < 16; u++){
                float4 wv4 = w[u];
                acc[4*u]   = fmaf(a, wv4.x, acc[4*u]);
                acc[4*u+1] = fmaf(a, wv4.y, acc[4*u+1]);
                acc[4*u+2] = fmaf(a, wv4.z, acc[4*u+2]);
                acc[4*u+3] = fmaf(a, wv4.w, acc[4*u+3]);
            }
        }
    }
    float4* o4 = (float4*)(g_F1 + (size_t)row*HID);
    #pragma unroll
    for (int u = 0; u < 16; u++)
        o4[u] = make_float4(acc[4*u], acc[4*u+1], acc[4*u+2], acc[4*u+3]);

    __threadfence();
    NBAR(ex);
    if (ltid == 0) atomicAdd(&g_f1done, 1);
}

// ---------------------------------------------------------------------------
// nbr task (unchanged from R8, precise gate)
// ---------------------------------------------------------------------------
__device__ void do_nbr(float* ws, int ltid, int ex, int id,
                       const float* __restrict__ point, float* __restrict__ out){
    float* px = ws; float* py = ws + NPP; float* pz = ws + 2*NPP;
    ull* keys = (ull*)(ws + 3*NPP);
    __shared__ int ncand[2][16];

    int cloud = id & 15, chunk = id >> 4;
    int c0g = cloud*MM + chunk*16;

    if (ltid == 0){
        while (vload(&g_prog[cloud]) < chunk*16 + 16) __nanosleep(128);
    }
    NBAR(ex);

    const float* P = point + (size_t)cloud*NPP*3;
    for (int i = ltid; i < NPP; i += 256){
        px[i] = P[i*3+0]; py[i] = P[i*3+1]; pz[i] = P[i*3+2];
    }
    if (ltid < 16) ncand[ex][ltid] = 0;
    NBAR(ex);

    for (int ci = 0; ci < 16; ci++){
        int c  = c0g + ci;
        int cl = __ldcg(&g_fps[c]);
        float cx = px[cl], cy = py[cl], cz = pz[cl];
        for (int i = ltid; i < NPP; i += 256){
            float d2 = d2f(px[i], py[i], pz[i], cx, cy, cz);
            if (d2 < R2){
                int p = atomicAdd(&ncand[ex][ci], 1);
                if (p < 512)
                    keys[p] = (((ull)__float_as_uint(d2)) << 32) | (unsigned)i;
            }
        }
        NBAR(ex);
        int n   = min(ncand[ex][ci], 512);
        int cnt = min(n, KK);
        if (ltid == 0) g_cnt[c] = cnt;
        for (int i = ltid; i < n; i += 256){
            ull k = keys[i];
            int rank = 0;
            for (int jj = 0; jj < n; jj++) rank += (keys[jj] < k);
            if (rank < KK) g_nbr[c*KK + rank] = (int)(k & 0xffffffffu);
        }
        for (int i = cnt + ltid; i < KK; i += 256) g_nbr[c*KK + i] = cl;
        NBAR(ex);
    }
    if (ltid < 16){
        int c = c0g + ltid; int cl = __ldcg(&g_fps[c]);
        out[OFF_C + c*3 + 0] = px[cl];
        out[OFF_C + c*3 + 1] = py[cl];
        out[OFF_C + c*3 + 2] = pz[cl];
        out[OFF_B + c] = (float)cloud;
    }
    __threadfence();
    NBAR(ex);
    if (ltid == 0) atomicExch(&g_flag[id], 1);
}

// ---------------------------------------------------------------------------
// mlp task (256 thr): 4 centers — R8 tiling EXACTLY, except h2's B operands
// come pre-paired from duplicated W2 in smem (no splats in h2).
// ---------------------------------------------------------------------------
__device__ void do_mlp(float* ws, float* smw, int ltid, int ex, int id,
                       const float* __restrict__ point,
                       const float* __restrict__ W3, float* __restrict__ out){
    float* buf  = ws;                 /* 16384 : [64][256] h1 then h2 */
    float* W2Ds = smw + SW2D;
    float* Wp   = smw + SWP;
    float* b2s  = smw + SB2;
    float* b3s  = smw + SB3;

    if (ltid == 0){
        int fl = ((id >> 6) << 4) | (id & 15);
        while (!(vload(&g_flag[fl]) && vload(&g_f1done) >= NF1)) __nanosleep(128);
    }
    NBAR(ex);

    int lane = ltid & 31;
    int cloud = id & 15;
    int seg   = id >> 4;
    int c0s   = cloud*MM + seg*4;
    const float* P = point + (size_t)cloud*NPP*3;

    int ci = ltid >> 6;
    int cl = __ldcg(&g_fps[c0s + ci]);
    int j  = __ldcg(&g_nbr[c0s*KK + ltid]);

    float dx = __fsub_rn(P[j*3+0], P[cl*3+0]);
    float dy = __fsub_rn(P[j*3+1], P[cl*3+1]);
    float dz = __fsub_rn(P[j*3+2], P[cl*3+2]);

    float h1[HID];
    const float4* fv = (const float4*)(g_F1 + (size_t)(cloud*NPP + j)*HID);
    #pragma unroll
    for (int q = 0; q < 16; q++){
        float4 v = __ldcg(fv + q);
        h1[4*q]=v.x; h1[4*q+1]=v.y; h1[4*q+2]=v.z; h1[4*q+3]=v.w;
    }
    #pragma unroll
    for (int i = 0; i < HID; i++){
        float v = h1[i];
        v = fmaf(dx, Wp[i],       v);
        v = fmaf(dy, Wp[64 + i],  v);
        v = fmaf(dz, Wp[128 + i], v);
        h1[i] = fmaxf(v, 0.f);
    }
    #pragma unroll
    for (int k = 0; k < HID; k++) buf[k*256 + ltid] = h1[k];
    NBAR(ex);

    int ow = (ltid >> 5)*8;

    /* h2 = relu(h1 @ W2 + b2) — B pre-paired from W2D (uniform LDS.128) */
    {
        ull acc[4][8];
        #pragma unroll
        for (int o = 0; o < 8; o++){
            ull bv = splat2(b2s[ow + o]);
            #pragma unroll
            for (int i = 0; i < 4; i++) acc[i][o] = bv;
        }
        const float* bptr = buf + 2*lane;
        #pragma unroll 4
        for (int k = 0; k < HID; k++){
            ull A2[4];
            #pragma unroll
            for (int i = 0; i < 4; i++)
                A2[i] = *(const ull*)(bptr + k*256 + 64*i);
            const float* wd = W2Ds + (k << 7) + 2*ow;
            ulonglong2 wq0 = *(const ulonglong2*)(wd);
            ulonglong2 wq1 = *(const ulonglong2*)(wd + 4);
            ulonglong2 wq2 = *(const ulonglong2*)(wd + 8);
            ulonglong2 wq3 = *(const ulonglong2*)(wd + 12);
            ull B2[8] = { wq0.x, wq0.y, wq1.x, wq1.y, wq2.x, wq2.y, wq3.x, wq3.y };
            #pragma unroll
            for (int o = 0; o < 8; o++)
                #pragma unroll
                for (int i = 0; i < 4; i++)
                    fma2(acc[i][o], A2[i], B2[o]);
        }
        NBAR(ex);
        #pragma unroll
        for (int o = 0; o < 8; o++)
            #pragma unroll
            for (int i = 0; i < 4; i++){
                float lo, hi; unpack2(acc[i][o], lo, hi);
                *(ull*)(buf + (ow+o)*256 + 2*lane + 64*i) =
                    pack2(fmaxf(lo, 0.f), fmaxf(hi, 0.f));
            }
        NBAR(ex);
    }

    int cnt4[4];
    #pragma unroll
    for (int i = 0; i < 4; i++) cnt4[i] = __ldcg(&g_cnt[c0s + i]);

    /* h3 = relu(h2 @ W3 + b3) — W3 from global (L1-resident), R8 exact */
    #pragma unroll
    for (int pass = 0; pass < 2; pass++){
        ull acc[4][8];
        #pragma unroll
        for (int o = 0; o < 8; o++){
            ull bv = splat2(b3s[pass*64 + ow + o]);
            #pragma unroll
            for (int i = 0; i < 4; i++) acc[i][o] = bv;
        }
        const float* bptr = buf + 2*lane;
        #pragma unroll 4
        for (int k = 0; k < HID; k++){
            ull A2[4];
            #pragma unroll
            for (int i = 0; i < 4; i++)
                A2[i] = *(const ull*)(bptr + k*256 + 64*i);
            const float* w = W3 + k*128 + pass*64 + ow;
            float4 w0 = *(const float4*)(w);
            float4 w1 = *(const float4*)(w + 4);
            ull B2[8] = { splat2(w0.x), splat2(w0.y), splat2(w0.z), splat2(w0.w),
                          splat2(w1.x), splat2(w1.y), splat2(w1.z), splat2(w1.w) };
            #pragma unroll
            for (int o = 0; o < 8; o++)
                #pragma unroll
                for (int i = 0; i < 4; i++)
                    fma2(acc[i][o], A2[i], B2[o]);
        }
        #pragma unroll
        for (int i = 0; i < 4; i++){
            bool v0 = (2*lane)     < cnt4[i];
            bool v1 = (2*lane + 1) < cnt4[i];
            #pragma unroll
            for (int o = 0; o < 8; o++){
                float lo, hi; unpack2(acc[i][o], lo, hi);
                lo = v0 ? fmaxf(lo, 0.f) : -3.402823466e38f;
                hi = v1 ? fmaxf(hi, 0.f) : -3.402823466e38f;
                float m = fmaxf(lo, hi);
                #pragma unroll
                for (int s = 16; s; s >>= 1)
                    m = fmaxf(m, __shfl_xor_sync(0xffffffffu, m, s));
                if (lane == 0)
                    out[(size_t)(c0s + i)*OUTD + pass*64 + ow + o] = m;
            }
        }
    }
}

// ---------------------------------------------------------------------------
// Init: reset queues/flags.
// ---------------------------------------------------------------------------
__global__ void init_kernel(){
    int t = blockIdx.x*blockDim.x + threadIdx.x;
    if (t == 0){ g_cf1 = 0; g_cnbr = 0; g_cmlp = 0; g_f1done = 0; }
    if (t < BB) g_prog[t] = 0;
    if (t < NTNBR) g_flag[t] = 0;
}

// ---------------------------------------------------------------------------
// Mega kernel.
// ---------------------------------------------------------------------------
__global__ void __launch_bounds__(NTHR,1) mega_kernel(
        const float* __restrict__ point, const float* __restrict__ xyz,
        const float* __restrict__ W1, const float* __restrict__ b1,
        const float* __restrict__ W2, const float* __restrict__ b2,
        const float* __restrict__ W3, const float* __restrict__ b3,
        float* __restrict__ out){
    extern __shared__ float sm[];
    int tid = threadIdx.x;
    __shared__ int s_ph[2], s_id[2];

    if (blockIdx.x < BB) do_fps(sm + SBUF0, tid, blockIdx.x, point);

    /* persistent weights: W2 duplicated for packed-pair loads */
    for (int i = tid; i < 4096; i += NTHR){
        float w = W2[i];
        int k = i >> 6, o = i & 63;
        sm[SW2D + (k << 7) + 2*o    ] = w;
        sm[SW2D + (k << 7) + 2*o + 1] = w;
    }
    if (tid < 192) sm[SWP + tid] = W1[4096 + tid];
    if (tid < 64)  sm[SB2 + tid] = b2[tid];
    if (tid < 128) sm[SB3 + tid] = b3[tid];
    __syncthreads();

    int ex   = tid >> 8;
    int ltid = tid & 255;
    float* ws = sm + (ex ? SBUF1 : SBUF0);

    for (;;){
        if (ltid == 0){
            int ph = -1, id = -1;
            if (vload(&g_cf1) < NF1){
                int t = atomicAdd(&g_cf1, 1);
                if (t < NF1){ ph = 0; id = t; }
            }
            if (ph < 0){
                int t = vload(&g_cnbr);
                if (t < NTNBR){
                    int cloud = t & 15, chunk = t >> 4;
                    if (vload(&g_prog[cloud]) >= chunk*16 + 16){
                        t = atomicAdd(&g_cnbr, 1);
                        if (t < NTNBR){ ph = 1; id = t; }
                    }
                }
            }
            if (ph < 0){
                int t = vload(&g_cmlp);
                if (t < NTMLP && vload(&g_f1done) >= NF1){
                    int fl = ((t >> 6) << 4) | (t & 15);
                    if (vload(&g_flag[fl])){
                        t = atomicAdd(&g_cmlp, 1);
                        if (t < NTMLP){ ph = 2; id = t; }
                    }
                }
            }
            if (ph < 0){
                if (vload(&g_cf1) >= NF1 && vload(&g_cnbr) >= NTNBR && vload(&g_cmlp) >= NTMLP)
                    ph = 3;
                else { __nanosleep(256); ph = 4; }
            }
            s_ph[ex] = ph; s_id[ex] = id;
        }
        NBAR(ex);
        int ph = s_ph[ex], id = s_id[ex];
        if (ph == 3) break;
        if      (ph == 0) do_f1 (ws, ltid, ex, id, xyz, W1, b1);
        else if (ph == 1) do_nbr(ws, ltid, ex, id, point, out);
        else if (ph == 2) do_mlp(ws, sm, ltid, ex, id, point, W3, out);
        NBAR(ex);
    }
}

extern "C" void kernel_launch(void* const* d_in, const int* in_sizes, int n_in,
                              void* d_out, int out_size){
    const float *xyz=nullptr, *point=nullptr, *W1=nullptr, *b1=nullptr,
                *W2=nullptr, *b2=nullptr, *W3=nullptr, *b3=nullptr;
    int n64 = 0;
    for (int i = 0; i < n_in; i++){
        switch (in_sizes[i]){
            case 4194304: xyz   = (const float*)d_in[i]; break;
            case 196608:  point = (const float*)d_in[i]; break;
            case 4288:    W1    = (const float*)d_in[i]; break;
            case 4096:    W2    = (const float*)d_in[i]; break;
            case 8192:    W3    = (const float*)d_in[i]; break;
            case 64:      if (n64++ == 0) b1 = (const float*)d_in[i];
                          else            b2 = (const float*)d_in[i]; break;
            case 128:     b3    = (const float*)d_in[i]; break;
            default: break;
        }
    }
    float* out = (float*)d_out;

    int smem = SMTOT*(int)sizeof(float);   /* 165,376 B */
    cudaFuncSetAttribute(mega_kernel, cudaFuncAttributeMaxDynamicSharedMemorySize, smem);

    init_kernel<<<4, 256>>>();
    mega_kernel<<<GRID, NTHR, smem>>>(point, xyz, W1, b1, W2, b2, W3, b3, out);
}

// round 15
// speedup vs baseline: 1.8038x; 1.0812x over previous
#include <cuda_runtime.h>
#include <cstdint>

#define BB   16
#define NPP  4096
#define CIN  64
#define MM   1024
#define KK   64
#define HID  64
#define OUTD 128
#define NC   (BB*MM)
#define R2   0.04f

#define OFF_C 2097152         /* NC*OUTD */
#define OFF_B 2146304         /* OFF_C + NC*3 */

#define NF1    256            /* f1 tasks: 256 rows each              */
#define NTNBR  1024           /* nbr tasks: 16 centers each (256 thr) */
#define NTMLP  4096           /* mlp tasks: 4 centers each (256 thr)  */
#define GRID   152
#define NTHR   512

/* smem layout (floats): two 16384-float half-workspaces, then weights */
#define SBUF0 0
#define SBUF1 16384
#define SW2   32768
#define SWP   36864
#define SB2   37056
#define SB3   37120
#define SMTOT 37248

#define NBAR(ex) asm volatile("bar.sync %0, %1;" :: "r"((ex)+1), "r"(256) : "memory")

typedef unsigned long long ull;

__device__ int   g_fps[NC];
__device__ int   g_nbr[NC*KK];
__device__ int   g_cnt[NC];
__device__ float g_F1[(size_t)BB*NPP*HID];
__device__ int   g_cf1, g_cnbr, g_cmlp, g_f1done;
__device__ int   g_prog[BB];
__device__ int   g_flag[NTNBR];

__device__ __forceinline__ float d2f(float ax,float ay,float az,float bx,float by,float bz){
    float dx=__fsub_rn(ax,bx), dy=__fsub_rn(ay,by), dz=__fsub_rn(az,bz);
    return __fadd_rn(__fadd_rn(__fmul_rn(dx,dx),__fmul_rn(dy,dy)),__fmul_rn(dz,dz));
}

/* ---- packed fp32x2 helpers (sm_103a, per-lane IEEE-exact) ---- */
__device__ __forceinline__ void fma2(ull &d, ull a, ull b){
    asm("fma.rn.f32x2 %0, %1, %2, %0;" : "+l"(d) : "l"(a), "l"(b));
}
__device__ __forceinline__ ull add2(ull a, ull b){
    ull r; asm("add.rn.f32x2 %0, %1, %2;" : "=l"(r) : "l"(a), "l"(b)); return r;
}
__device__ __forceinline__ ull mul2(ull a, ull b){
    ull r; asm("mul.rn.f32x2 %0, %1, %2;" : "=l"(r) : "l"(a), "l"(b)); return r;
}
__device__ __forceinline__ ull splat2(float x){
    ull r; unsigned u = __float_as_uint(x);
    asm("mov.b64 %0, {%1, %1};" : "=l"(r) : "r"(u)); return r;
}
__device__ __forceinline__ void unpack2(ull v, float &lo, float &hi){
    unsigned a,b; asm("mov.b64 {%0, %1}, %2;" : "=r"(a), "=r"(b) : "l"(v));
    lo = __uint_as_float(a); hi = __uint_as_float(b);
}
__device__ __forceinline__ ull pack2(float lo, float hi){
    ull r;
    asm("mov.b64 %0, {%1, %2};" : "=l"(r) : "r"(__float_as_uint(lo)), "r"(__float_as_uint(hi)));
    return r;
}
__device__ __forceinline__ int vload(const int* p){ return *(volatile const int*)p; }

// ---------------------------------------------------------------------------
// FPS producer (R8 unchanged)
// ---------------------------------------------------------------------------
__device__ void do_fps(float* sm, int tid, int b, const float* __restrict__ point){
    float* px = sm; float* py = sm + NPP; float* pz = sm + 2*NPP;
    __shared__ ull wpS[2][32];
    int lane = tid & 31, warp = tid >> 5;

    const float* P = point + (size_t)b*NPP*3;
    float x[8], y[8], z[8], d[8];
    #pragma unroll
    for (int r = 0; r < 8; r++){
        int i = tid + r*NTHR;
        float a0 = P[i*3+0], a1 = P[i*3+1], a2 = P[i*3+2];
        px[i] = a0; py[i] = a1; pz[i] = a2;
        x[r] = a0; y[r] = a1; z[r] = a2;
        d[r] = 3.402823466e38f;
    }
    ull xp[4], yp[4], zp[4];
    #pragma unroll
    for (int g = 0; g < 4; g++){
        xp[g] = pack2(x[2*g], x[2*g+1]);
        yp[g] = pack2(y[2*g], y[2*g+1]);
        zp[g] = pack2(z[2*g], z[2*g+1]);
    }
    if (tid < 64) ((ull*)wpS)[tid] = 0ull;
    if (tid == 0) g_fps[b*MM] = 0;
    __syncthreads();

    int last = 0, par = 0;
    for (int m = 1; m < MM; m++){
        float cx = px[last], cy = py[last], cz = pz[last];
        ull ncx = splat2(-cx), ncy = splat2(-cy), ncz = splat2(-cz);

        float bv = -1.f;
        #pragma unroll
        for (int g = 0; g < 4; g++){
            ull dx = add2(xp[g], ncx);
            ull dy = add2(yp[g], ncy);
            ull dz = add2(zp[g], ncz);
            ull ss = add2(add2(mul2(dx,dx), mul2(dy,dy)), mul2(dz,dz));
            float s0, s1; unpack2(ss, s0, s1);
            float v0 = fminf(d[2*g  ], s0); d[2*g  ] = v0;
            float v1 = fminf(d[2*g+1], s1); d[2*g+1] = v1;
            bv = fmaxf(bv, fmaxf(v0, v1));
        }
        unsigned bits = __float_as_uint(bv);
        unsigned wmax = __reduce_max_sync(0xffffffffu, bits);
        unsigned cand = 0xffffffffu;
        if (bits == wmax){
            #pragma unroll
            for (int r = 7; r >= 0; r--)
                if (d[r] == bv) cand = (unsigned)(tid + r*NTHR);
        }
        unsigned widx = __reduce_min_sync(0xffffffffu, cand);
        if (lane == 0) wpS[par][warp] = (((ull)wmax) << 32) | widx;
        __syncthreads();
        ull v = wpS[par][lane];
        unsigned hb = (unsigned)(v >> 32), lw = (unsigned)v;
        unsigned gmax = __reduce_max_sync(0xffffffffu, hb);
        unsigned c2   = (hb == gmax) ? lw : 0xffffffffu;
        unsigned gidx = __reduce_min_sync(0xffffffffu, c2);
        last = (int)gidx;
        if (tid == 0){
            g_fps[b*MM + m] = last;
            if ((m & 15) == 15){ __threadfence(); atomicExch(&g_prog[b], m + 1); }
        }
        par ^= 1;
    }
}

// ---------------------------------------------------------------------------
// F1 task (R8 unchanged)
// ---------------------------------------------------------------------------
__device__ void do_f1(float* ws, int ltid, int ex, int id,
                      const float* __restrict__ xyz,
                      const float* __restrict__ W1,
                      const float* __restrict__ b1){
    float* W1s = ws;
    for (int i = ltid; i < CIN*HID; i += 256) W1s[i] = W1[i];
    if (ltid < HID) W1s[4096 + ltid] = b1[ltid];
    NBAR(ex);

    int row = id*256 + ltid;
    float acc[HID];
    #pragma unroll
    for (int o = 0; o < HID; o++) acc[o] = W1s[4096 + o];
    const float4* xr = (const float4*)(xyz + (size_t)row*CIN);
    #pragma unroll
    for (int q = 0; q < 16; q++){
        float4 xv = xr[q];
        float av[4] = {xv.x, xv.y, xv.z, xv.w};
        #pragma unroll
        for (int t = 0; t < 4; t++){
            float a = av[t];
            const float4* w = (const float4*)(W1s + (q*4+t)*HID);
            #pragma unroll
            for (int u = 0; u < 16; u++){
                float4 wv4 = w[u];
                acc[4*u]   = fmaf(a, wv4.x, acc[4*u]);
                acc[4*u+1] = fmaf(a, wv4.y, acc[4*u+1]);
                acc[4*u+2] = fmaf(a, wv4.z, acc[4*u+2]);
                acc[4*u+3] = fmaf(a, wv4.w, acc[4*u+3]);
            }
        }
    }
    float4* o4 = (float4*)(g_F1 + (size_t)row*HID);
    #pragma unroll
    for (int u = 0; u < 16; u++)
        o4[u] = make_float4(acc[4*u], acc[4*u+1], acc[4*u+2], acc[4*u+3]);

    __threadfence();
    NBAR(ex);
    if (ltid == 0) atomicAdd(&g_f1done, 1);
}

// ---------------------------------------------------------------------------
// nbr task: scan packed into f32x2 (bit-identical d2), rest unchanged.
// ---------------------------------------------------------------------------
__device__ void do_nbr(float* ws, int ltid, int ex, int id,
                       const float* __restrict__ point, float* __restrict__ out){
    float* px = ws; float* py = ws + NPP; float* pz = ws + 2*NPP;
    ull* keys = (ull*)(ws + 3*NPP);
    __shared__ int ncand[2][16];

    int cloud = id & 15, chunk = id >> 4;
    int c0g = cloud*MM + chunk*16;

    if (ltid == 0){
        while (vload(&g_prog[cloud]) < chunk*16 + 16) __nanosleep(128);
    }
    NBAR(ex);

    const float* P = point + (size_t)cloud*NPP*3;
    for (int i = ltid; i < NPP; i += 256){
        px[i] = P[i*3+0]; py[i] = P[i*3+1]; pz[i] = P[i*3+2];
    }
    if (ltid < 16) ncand[ex][ltid] = 0;
    NBAR(ex);

    for (int ci = 0; ci < 16; ci++){
        int c  = c0g + ci;
        int cl = __ldcg(&g_fps[c]);
        float cx = px[cl], cy = py[cl], cz = pz[cl];
        ull ncx = splat2(-cx), ncy = splat2(-cy), ncz = splat2(-cz);
        for (int t = ltid; t < NPP/2; t += 256){
            ull xx = *(const ull*)(px + 2*t);
            ull yy = *(const ull*)(py + 2*t);
            ull zz = *(const ull*)(pz + 2*t);
            ull dx = add2(xx, ncx);
            ull dy = add2(yy, ncy);
            ull dz = add2(zz, ncz);
            ull ss = add2(add2(mul2(dx,dx), mul2(dy,dy)), mul2(dz,dz));
            float s0, s1; unpack2(ss, s0, s1);
            if (s0 < R2){
                int p = atomicAdd(&ncand[ex][ci], 1);
                if (p < 512)
                    keys[p] = (((ull)__float_as_uint(s0)) << 32) | (unsigned)(2*t);
            }
            if (s1 < R2){
                int p = atomicAdd(&ncand[ex][ci], 1);
                if (p < 512)
                    keys[p] = (((ull)__float_as_uint(s1)) << 32) | (unsigned)(2*t + 1);
            }
        }
        NBAR(ex);
        int n   = min(ncand[ex][ci], 512);
        int cnt = min(n, KK);
        if (ltid == 0) g_cnt[c] = cnt;
        for (int i = ltid; i < n; i += 256){
            ull k = keys[i];
            int rank = 0;
            for (int jj = 0; jj < n; jj++) rank += (keys[jj] < k);
            if (rank < KK) g_nbr[c*KK + rank] = (int)(k & 0xffffffffu);
        }
        for (int i = cnt + ltid; i < KK; i += 256) g_nbr[c*KK + i] = cl;
        NBAR(ex);
    }
    if (ltid < 16){
        int c = c0g + ltid; int cl = __ldcg(&g_fps[c]);
        out[OFF_C + c*3 + 0] = px[cl];
        out[OFF_C + c*3 + 1] = py[cl];
        out[OFF_C + c*3 + 2] = pz[cl];
        out[OFF_B + c] = (float)cloud;
    }
    __threadfence();
    NBAR(ex);
    if (ltid == 0) atomicExch(&g_flag[id], 1);
}

// ---------------------------------------------------------------------------
// mlp task (256 thr): R8 tiling exactly; h3 epilogue max via __reduce_max_sync
// (valid: post-relu values >= 0, masked slots -> 0u, cnt >= 1 always).
// ---------------------------------------------------------------------------
__device__ void do_mlp(float* ws, float* smw, int ltid, int ex, int id,
                       const float* __restrict__ point,
                       const float* __restrict__ W3, float* __restrict__ out){
    float* buf = ws;                 /* 16384 : [64][256] h1 then h2 */
    float* W2s = smw + SW2;
    float* Wp  = smw + SWP;
    float* b2s = smw + SB2;
    float* b3s = smw + SB3;

    if (ltid == 0){
        int fl = ((id >> 6) << 4) | (id & 15);
        while (!(vload(&g_flag[fl]) && vload(&g_f1done) >= NF1)) __nanosleep(128);
    }
    NBAR(ex);

    int lane = ltid & 31;
    int cloud = id & 15;
    int seg   = id >> 4;
    int c0s   = cloud*MM + seg*4;
    const float* P = point + (size_t)cloud*NPP*3;

    int ci = ltid >> 6;
    int cl = __ldcg(&g_fps[c0s + ci]);
    int j  = __ldcg(&g_nbr[c0s*KK + ltid]);

    float dx = __fsub_rn(P[j*3+0], P[cl*3+0]);
    float dy = __fsub_rn(P[j*3+1], P[cl*3+1]);
    float dz = __fsub_rn(P[j*3+2], P[cl*3+2]);

    float h1[HID];
    const float4* fv = (const float4*)(g_F1 + (size_t)(cloud*NPP + j)*HID);
    #pragma unroll
    for (int q = 0; q < 16; q++){
        float4 v = __ldcg(fv + q);
        h1[4*q]=v.x; h1[4*q+1]=v.y; h1[4*q+2]=v.z; h1[4*q+3]=v.w;
    }
    #pragma unroll
    for (int i = 0; i < HID; i++){
        float v = h1[i];
        v = fmaf(dx, Wp[i],       v);
        v = fmaf(dy, Wp[64 + i],  v);
        v = fmaf(dz, Wp[128 + i], v);
        h1[i] = fmaxf(v, 0.f);
    }
    #pragma unroll
    for (int k = 0; k < HID; k++) buf[k*256 + ltid] = h1[k];
    NBAR(ex);

    int ow = (ltid >> 5)*8;

    /* h2 = relu(h1 @ W2 + b2) */
    {
        ull acc[4][8];
        #pragma unroll
        for (int o = 0; o < 8; o++){
            ull bv = splat2(b2s[ow + o]);
            #pragma unroll
            for (int i = 0; i < 4; i++) acc[i][o] = bv;
        }
        const float* bptr = buf + 2*lane;
        #pragma unroll 4
        for (int k = 0; k < HID; k++){
            ull A2[4];
            #pragma unroll
            for (int i = 0; i < 4; i++)
                A2[i] = *(const ull*)(bptr + k*256 + 64*i);
            float4 w0 = *(const float4*)(W2s + k*64 + ow);
            float4 w1 = *(const float4*)(W2s + k*64 + ow + 4);
            ull B2[8] = { splat2(w0.x), splat2(w0.y), splat2(w0.z), splat2(w0.w),
                          splat2(w1.x), splat2(w1.y), splat2(w1.z), splat2(w1.w) };
            #pragma unroll
            for (int o = 0; o < 8; o++)
                #pragma unroll
                for (int i = 0; i < 4; i++)
                    fma2(acc[i][o], A2[i], B2[o]);
        }
        NBAR(ex);
        #pragma unroll
        for (int o = 0; o < 8; o++)
            #pragma unroll
            for (int i = 0; i < 4; i++){
                float lo, hi; unpack2(acc[i][o], lo, hi);
                *(ull*)(buf + (ow+o)*256 + 2*lane + 64*i) =
                    pack2(fmaxf(lo, 0.f), fmaxf(hi, 0.f));
            }
        NBAR(ex);
    }

    int cnt4[4];
    #pragma unroll
    for (int i = 0; i < 4; i++) cnt4[i] = __ldcg(&g_cnt[c0s + i]);

    /* h3 = relu(h2 @ W3 + b3) — W3 from global (L1-resident) */
    #pragma unroll
    for (int pass = 0; pass < 2; pass++){
        ull acc[4][8];
        #pragma unroll
        for (int o = 0; o < 8; o++){
            ull bv = splat2(b3s[pass*64 + ow + o]);
            #pragma unroll
            for (int i = 0; i < 4; i++) acc[i][o] = bv;
        }
        const float* bptr = buf + 2*lane;
        #pragma unroll 4
        for (int k = 0; k < HID; k++){
            ull A2[4];
            #pragma unroll
            for (int i = 0; i < 4; i++)
                A2[i] = *(const ull*)(bptr + k*256 + 64*i);
            const float* w = W3 + k*128 + pass*64 + ow;
            float4 w0 = *(const float4*)(w);
            float4 w1 = *(const float4*)(w + 4);
            ull B2[8] = { splat2(w0.x), splat2(w0.y), splat2(w0.z), splat2(w0.w),
                          splat2(w1.x), splat2(w1.y), splat2(w1.z), splat2(w1.w) };
            #pragma unroll
            for (int o = 0; o < 8; o++)
                #pragma unroll
                for (int i = 0; i < 4; i++)
                    fma2(acc[i][o], A2[i], B2[o]);
        }
        #pragma unroll
        for (int i = 0; i < 4; i++){
            bool v0 = (2*lane)     < cnt4[i];
            bool v1 = (2*lane + 1) < cnt4[i];
            #pragma unroll
            for (int o = 0; o < 8; o++){
                float lo, hi; unpack2(acc[i][o], lo, hi);
                unsigned b0 = v0 ? __float_as_uint(fmaxf(lo, 0.f)) : 0u;
                unsigned b1 = v1 ? __float_as_uint(fmaxf(hi, 0.f)) : 0u;
                unsigned m  = __reduce_max_sync(0xffffffffu, b0 > b1 ? b0 : b1);
                if (lane == 0)
                    out[(size_t)(c0s + i)*OUTD + pass*64 + ow + o] = __uint_as_float(m);
            }
        }
    }
}

// ---------------------------------------------------------------------------
// Init: reset queues/flags.
// ---------------------------------------------------------------------------
__global__ void init_kernel(){
    int t = blockIdx.x*blockDim.x + threadIdx.x;
    if (t == 0){ g_cf1 = 0; g_cnbr = 0; g_cmlp = 0; g_f1done = 0; }
    if (t < BB) g_prog[t] = 0;
    if (t < NTNBR) g_flag[t] = 0;
}

// ---------------------------------------------------------------------------
// Mega kernel: FPS blocks 0..15, then TWO 256-thread task executors per block.
// ---------------------------------------------------------------------------
__global__ void __launch_bounds__(NTHR,1) mega_kernel(
        const float* __restrict__ point, const float* __restrict__ xyz,
        const float* __restrict__ W1, const float* __restrict__ b1,
        const float* __restrict__ W2, const float* __restrict__ b2,
        const float* __restrict__ W3, const float* __restrict__ b3,
        float* __restrict__ out){
    extern __shared__ float sm[];
    int tid = threadIdx.x;
    __shared__ int s_ph[2], s_id[2];

    if (blockIdx.x < BB) do_fps(sm + SBUF0, tid, blockIdx.x, point);

    /* persistent weights (shared read-only by both executors) */
    for (int i = tid; i < 4096; i += NTHR) sm[SW2 + i] = W2[i];
    if (tid < 192) sm[SWP + tid] = W1[4096 + tid];
    if (tid < 64)  sm[SB2 + tid] = b2[tid];
    if (tid < 128) sm[SB3 + tid] = b3[tid];
    __syncthreads();

    int ex   = tid >> 8;
    int ltid = tid & 255;
    float* ws = sm + (ex ? SBUF1 : SBUF0);

    for (;;){
        if (ltid == 0){
            int ph = -1, id = -1;
            if (vload(&g_cf1) < NF1){
                int t = atomicAdd(&g_cf1, 1);
                if (t < NF1){ ph = 0; id = t; }
            }
            if (ph < 0){
                int t = vload(&g_cnbr);
                if (t < NTNBR){
                    int cloud = t & 15, chunk = t >> 4;
                    if (vload(&g_prog[cloud]) >= chunk*16 + 16){
                        t = atomicAdd(&g_cnbr, 1);
                        if (t < NTNBR){ ph = 1; id = t; }
                    }
                }
            }
            if (ph < 0){
                int t = vload(&g_cmlp);
                if (t < NTMLP && vload(&g_f1done) >= NF1){
                    int fl = ((t >> 6) << 4) | (t & 15);
                    if (vload(&g_flag[fl])){
                        t = atomicAdd(&g_cmlp, 1);
                        if (t < NTMLP){ ph = 2; id = t; }
                    }
                }
            }
            if (ph < 0){
                if (vload(&g_cf1) >= NF1 && vload(&g_cnbr) >= NTNBR && vload(&g_cmlp) >= NTMLP)
                    ph = 3;
                else { __nanosleep(256); ph = 4; }
            }
            s_ph[ex] = ph; s_id[ex] = id;
        }
        NBAR(ex);
        int ph = s_ph[ex], id = s_id[ex];
        if (ph == 3) break;
        if      (ph == 0) do_f1 (ws, ltid, ex, id, xyz, W1, b1);
        else if (ph == 1) do_nbr(ws, ltid, ex, id, point, out);
        else if (ph == 2) do_mlp(ws, sm, ltid, ex, id, point, W3, out);
        NBAR(ex);
    }
}

extern "C" void kernel_launch(void* const* d_in, const int* in_sizes, int n_in,
                              void* d_out, int out_size){
    const float *xyz=nullptr, *point=nullptr, *W1=nullptr, *b1=nullptr,
                *W2=nullptr, *b2=nullptr, *W3=nullptr, *b3=nullptr;
    int n64 = 0;
    for (int i = 0; i < n_in; i++){
        switch (in_sizes[i]){
            case 4194304: xyz   = (const float*)d_in[i]; break;
            case 196608:  point = (const float*)d_in[i]; break;
            case 4288:    W1    = (const float*)d_in[i]; break;
            case 4096:    W2    = (const float*)d_in[i]; break;
            case 8192:    W3    = (const float*)d_in[i]; break;
            case 64:      if (n64++ == 0) b1 = (const float*)d_in[i];
                          else            b2 = (const float*)d_in[i]; break;
            case 128:     b3    = (const float*)d_in[i]; break;
            default: break;
        }
    }
    float* out = (float*)d_out;

    int smem = SMTOT*(int)sizeof(float);   /* 148,992 B */
    cudaFuncSetAttribute(mega_kernel, cudaFuncAttributeMaxDynamicSharedMemorySize, smem);

    init_kernel<<<4, 256>>>();
    mega_kernel<<<GRID, NTHR, smem>>>(point, xyz, W1, b1, W2, b2, W3, b3, out);
}